// round 17
// baseline (speedup 1.0000x reference)
#include <cuda_runtime.h>
#include <cstdint>

// Motion loss on GB300: persistent software-pipelined blocks (R15 structure)
// with UNNORMALIZED quaternion FK: R(q)=R(q^) so the Hamilton-product chain
// runs on raw quats (critical path ~45cyc/joint vs ~100 with per-joint
// normalization). Norm^2 products are carried multiplicatively (packed) and
// rotations use two_s = 2/np off the critical path. Rot loss via
// |q^x-q^y|^2 = 2 - 2 dot(qx,qy) rsqrt(|qx|^2 |qy|^2) (one scalar rsqrt,
// off-path). Both skeletons packed in f32x2 throughout.

namespace {

constexpr int ROW   = 99;                  // floats per row (per array)
constexpr int TROWS = 64;                  // rows per tile
constexpr int TPB   = 128;                 // 2 threads per row
constexpr int NBT   = 64 * 2048;           // 131072 rows
constexpr int NT    = NBT / TROWS;         // 2048 tiles
constexpr int GRID  = 296;                 // persistent blocks (2/SM x 148)
constexpr int TILE_F4 = TROWS * ROW / 4;   // 1584 float4 per array per tile

constexpr int BUF_U64   = TROWS * ROW;     // 6336 u64 pairs per buffer
constexpr int BONES_OFF = 2 * BUF_U64;     // u64 units: bones buf0/buf1 (72 each)
constexpr int G9_OFF    = BONES_OFF + 2 * 72;
constexpr int SMEM_U64  = G9_OFF + TROWS * 8 + 8;
constexpr int SMEM_BYTES = SMEM_U64 * 8;   // ~106.8 KB -> 2 blocks/SM

// joint terms owned by exactly one thread -> full weight
constexpr float S1 = 1.0f / (float(NBT) * 96.0f);
constexpr float S2 = 2.5f / (float(NBT) * 72.0f);
// root terms computed by both threads of a row -> half weight
constexpr float S1h  = 0.5f * S1;
constexpr float S23h = 0.5f * (S2 + 1.0f / (float(NBT) * 3.0f));

} // namespace

__device__ float    g_partials[GRID];
__device__ unsigned g_count = 0;

using u32 = unsigned int;
using u64 = unsigned long long;

// ---- packed f32x2 primitives ----
__device__ __forceinline__ u64 pk2(float lo, float hi) {
    u64 r;
    asm("mov.b64 %0, {%1, %2};" : "=l"(r)
        : "r"(__float_as_uint(lo)), "r"(__float_as_uint(hi)));
    return r;
}
__device__ __forceinline__ void upk2(u64 v, float& lo, float& hi) {
    u32 a, b;
    asm("mov.b64 {%0, %1}, %2;" : "=r"(a), "=r"(b) : "l"(v));
    lo = __uint_as_float(a); hi = __uint_as_float(b);
}
__device__ __forceinline__ u64 fm2(u64 a, u64 b, u64 c) {
    u64 r; asm("fma.rn.f32x2 %0, %1, %2, %3;" : "=l"(r) : "l"(a), "l"(b), "l"(c));
    return r;
}
__device__ __forceinline__ u64 ml2(u64 a, u64 b) {
    u64 r; asm("mul.rn.f32x2 %0, %1, %2;" : "=l"(r) : "l"(a), "l"(b));
    return r;
}
__device__ __forceinline__ u64 ad2(u64 a, u64 b) {
    u64 r; asm("add.rn.f32x2 %0, %1, %2;" : "=l"(r) : "l"(a), "l"(b));
    return r;
}

constexpr u64 NEG1 = 0xBF800000BF800000ULL;

// packed transform: UNNORMALIZED quat product, translation, norm^2 product
struct PX { u64 qw, qx, qy, qz, tx, ty, tz, np; };

// (hi-lo)^2 accumulate
__device__ __forceinline__ void d2(u64 v, float& s) {
    float a, b; upk2(v, a, b);
    float d = a - b;
    s = fmaf(d, d, s);
}

// rot loss for a raw packed quat: |q^x - q^y|^2 = 2 - 2 dot/rsqrt-prod
__device__ __forceinline__ void rot_loss(u64 w, u64 x, u64 y, u64 z, u64 n2,
                                         float wgt, float& acc) {
    float wa, wb, xa, xb, ya, yb, za, zb, na, nb;
    upk2(w, wa, wb); upk2(x, xa, xb); upk2(y, ya, yb); upk2(z, za, zb);
    upk2(n2, na, nb);
    float dot = fmaf(za, zb, fmaf(ya, yb, fmaf(xa, xb, wa * wb)));
    float rl  = fmaf(-2.f * dot, rsqrtf(na * nb), 2.f);
    acc = fmaf(wgt, rl, acc);
}

// one non-root joint, unnormalized compose; j compile-time at call site.
// Alias-safe for O == P (quat fields read before written via temps).
__device__ __forceinline__ void jstep(const u64* __restrict__ r,
                                      const u64* __restrict__ bn,
                                      int j, const PX& P, PX& O, float& acc) {
    u64 w = r[4*j+0], x = r[4*j+1], y = r[4*j+2], z = r[4*j+3];
    u64 n2 = fm2(z, z, fm2(y, y, fm2(x, x, ml2(w, w))));

    rot_loss(w, x, y, z, n2, S1, acc);

    u64 bx = bn[3*j+0], by = bn[3*j+1], bz = bn[3*j+2];

    // two_s = 2 / |P.Q|^2 per skeleton (off critical path)
    float npa, npb; upk2(P.np, npa, npb);
    u64 two_s = pk2(__fdividef(2.f, npa), __fdividef(2.f, npb));

    u64 nx = ml2(P.qx, NEG1), ny = ml2(P.qy, NEG1), nz = ml2(P.qz, NEG1);
    // c = u x b
    u64 cx = fm2(P.qy, bz, ml2(nz, by));
    u64 cy = fm2(P.qz, bx, ml2(nx, bz));
    u64 cz = fm2(P.qx, by, ml2(ny, bx));
    // s = w*c + u x c
    u64 sx = fm2(P.qw, cx, fm2(P.qy, cz, ml2(nz, cy)));
    u64 sy = fm2(P.qw, cy, fm2(P.qz, cx, ml2(nx, cz)));
    u64 sz = fm2(P.qw, cz, fm2(P.qx, cy, ml2(ny, cx)));
    // T = b + two_s*s + P.T
    u64 otx = fm2(two_s, sx, ad2(bx, P.tx));
    u64 oty = fm2(two_s, sy, ad2(by, P.ty));
    u64 otz = fm2(two_s, sz, ad2(bz, P.tz));
    // Q = P.Q * l  (raw Hamilton product — THE critical chain, depth 4 fma)
    u64 rw = fm2(P.qw, w, fm2(nx, x, fm2(ny, y, ml2(nz, z))));
    u64 rx = fm2(P.qw, x, fm2(w, P.qx, fm2(P.qy, z, ml2(nz, y))));
    u64 ry = fm2(P.qw, y, fm2(w, P.qy, fm2(P.qz, x, ml2(nx, z))));
    u64 rz = fm2(P.qw, z, fm2(w, P.qz, fm2(P.qx, y, ml2(ny, x))));
    u64 onp = ml2(P.np, n2);

    O.qw = rw; O.qx = rx; O.qy = ry; O.qz = rz;
    O.tx = otx; O.ty = oty; O.tz = otz; O.np = onp;

    float t = 0.f;
    d2(otx, t); d2(oty, t); d2(otz, t);
    acc = fmaf(S2, t, acc);
}

// ---- staging chunks: last absolute index (12) is the only guarded one ----
template<int K0, int N>
__device__ __forceinline__ void ldg_chunk(const float4* __restrict__ gx,
                                          const float4* __restrict__ gy,
                                          int tid, float4* ra, float4* rc) {
#pragma unroll
    for (int kk = 0; kk < N; ++kk) {
        int i = tid + (K0 + kk) * TPB;
        if (K0 + kk < 12 || tid < TILE_F4 - 12 * TPB) {
            ra[kk] = __ldg(gx + i);
            rc[kk] = __ldg(gy + i);
        }
    }
}
template<int K0, int N>
__device__ __forceinline__ void sts_chunk(float4* __restrict__ d, int tid,
                                          const float4* ra, const float4* rc) {
#pragma unroll
    for (int kk = 0; kk < N; ++kk) {
        int i = tid + (K0 + kk) * TPB;
        if (K0 + kk < 12 || tid < TILE_F4 - 12 * TPB) {
            d[2*i + 0] = make_float4(ra[kk].x, rc[kk].x, ra[kk].y, rc[kk].y);
            d[2*i + 1] = make_float4(ra[kk].z, rc[kk].z, ra[kk].w, rc[kk].w);
        }
    }
}

__global__ __launch_bounds__(TPB, 2)
void motion_loss_kernel(const float* __restrict__ Ym,
                        const float* __restrict__ Xm,
                        const float* __restrict__ Yt,
                        const float* __restrict__ Xt,
                        float* __restrict__ out)
{
    extern __shared__ float smf[];
    u64* smu = (u64*)smf;
    const int tid = threadIdx.x;
    const int bid = blockIdx.x;

    const int lane = tid & 31;
    const int wid  = tid >> 5;                 // 0..3
    const int isB  = wid & 1;                  // even warp = half A, odd = half B
    const int row  = (wid >> 1) * 32 + lane;   // row within tile (0..63)
    const unsigned FULL = 0xffffffffu;

    float acc = 0.f;

    // ---- prologue: stage tile `bid` into buffer 0 ----
    {
        const float4* gx = (const float4*)(Xm + (size_t)bid * TROWS * ROW);
        const float4* gy = (const float4*)(Ym + (size_t)bid * TROWS * ROW);
        float4* d = (float4*)smu;
#pragma unroll
        for (int kk = 0; kk < 13; ++kk) {
            int i = tid + kk * TPB;
            if (kk < 12 || tid < TILE_F4 - 12 * TPB) {
                float4 a = __ldg(gx + i);
                float4 c = __ldg(gy + i);
                d[2*i + 0] = make_float4(a.x, c.x, a.y, c.y);
                d[2*i + 1] = make_float4(a.z, c.z, a.w, c.w);
            }
        }
        const int b0 = bid >> 5;               // 32 tiles per batch item
        if (tid < 72) {
            float2* bt = (float2*)(smu + BONES_OFF);
            bt[tid] = make_float2(Xt[b0 * 72 + tid], Yt[b0 * 72 + tid]);
        }
    }
    __syncthreads();

    // ---- persistent pipelined main loop ----
    int kb = 0;
    for (int t = bid; t < NT; t += GRID, kb ^= 1) {
        const bool pre = (t + GRID) < NT;

        const u64* r  = smu + (size_t)kb * BUF_U64 + (size_t)row * ROW;
        const u64* bn = smu + BONES_OFF + kb * 72;
        u64* g9s      = smu + G9_OFF + (size_t)row * 8;

        const float4* gx = (const float4*)(Xm + (size_t)(t + GRID) * TROWS * ROW);
        const float4* gy = (const float4*)(Ym + (size_t)(t + GRID) * TROWS * ROW);
        float4*  dN  = (float4*)(smu + (size_t)(kb ^ 1) * BUF_U64);
        float2*  btN = (float2*)(smu + BONES_OFF + (kb ^ 1) * 72);
        const int bnext = (t + GRID) >> 5;

        float4 ra[5], rc[5];
        float bna = 0.f, bnc = 0.f;

        if (pre) {
            ldg_chunk<0, 4>(gx, gy, tid, ra, rc);
            if (tid < 72) { bna = Xt[bnext * 72 + tid]; bnc = Yt[bnext * 72 + tid]; }
        }

        // ---- root: raw quat + raw position; np = |q0|^2 ----
        PX P0;
        {
            u64 w = r[0], x = r[1], y = r[2], z = r[3];
            u64 n2 = fm2(z, z, fm2(y, y, fm2(x, x, ml2(w, w))));
            rot_loss(w, x, y, z, n2, S1h, acc);

            P0.qw = w; P0.qx = x; P0.qy = y; P0.qz = z; P0.np = n2;
            P0.tx = r[96]; P0.ty = r[97]; P0.tz = r[98];
            float tt = 0.f;
            d2(P0.tx, tt); d2(P0.ty, tt); d2(P0.tz, tt);
            acc = fmaf(S23h, tt, acc);
        }

        // ---- phase 1 ----
        PX G9v;
        if (!isB) {
            jstep(r, bn, 3, P0, G9v, acc);
            jstep(r, bn, 6, G9v, G9v, acc);
            jstep(r, bn, 9, G9v, G9v, acc);
            g9s[0] = G9v.qw; g9s[1] = G9v.qx; g9s[2] = G9v.qy; g9s[3] = G9v.qz;
            g9s[4] = G9v.tx; g9s[5] = G9v.ty; g9s[6] = G9v.tz; g9s[7] = G9v.np;
        } else {
            PX C;
            jstep(r, bn,  2, P0, C, acc);
            jstep(r, bn,  5, C,  C, acc);
            jstep(r, bn,  8, C,  C, acc);
            jstep(r, bn, 11, C,  C, acc);
        }

        if (pre) {
            sts_chunk<0, 4>(dN, tid, ra, rc);
            ldg_chunk<4, 5>(gx, gy, tid, ra, rc);
        }
        __syncthreads();                       // publish G9 (staging unharmed)

        // ---- phase 2, part 1 ----
        PX C1, C2;
        if (!isB) {
            jstep(r, bn,  1, P0,  C1, acc);
            jstep(r, bn, 13, G9v, C2, acc);
            jstep(r, bn,  4, C1,  C1, acc);
            jstep(r, bn, 16, C2,  C2, acc);
        } else {
            PX P9;
            P9.qw = g9s[0]; P9.qx = g9s[1]; P9.qy = g9s[2]; P9.qz = g9s[3];
            P9.tx = g9s[4]; P9.ty = g9s[5]; P9.tz = g9s[6]; P9.np = g9s[7];
            jstep(r, bn, 12, P9, C1, acc);
            jstep(r, bn, 14, P9, C2, acc);
            jstep(r, bn, 15, C1, C1, acc);
            jstep(r, bn, 17, C2, C2, acc);
        }

        if (pre) {
            sts_chunk<4, 5>(dN, tid, ra, rc);
            ldg_chunk<9, 4>(gx, gy, tid, ra, rc);
            if (tid < 72) btN[tid] = make_float2(bna, bnc);
        }

        // ---- phase 2, part 2 ----
        if (!isB) {
            jstep(r, bn,  7, C1, C1, acc);
            jstep(r, bn, 18, C2, C2, acc);
            jstep(r, bn, 10, C1, C1, acc);
            jstep(r, bn, 20, C2, C2, acc);
            jstep(r, bn, 22, C2, C2, acc);
        } else {
            jstep(r, bn, 19, C2, C2, acc);
            jstep(r, bn, 21, C2, C2, acc);
            jstep(r, bn, 23, C2, C2, acc);
        }

        if (pre) sts_chunk<9, 4>(dN, tid, ra, rc);
        __syncthreads();                       // next buffer staged; current reads done
    }

    // ---- block reduction (4 warps) ----
    #pragma unroll
    for (int o = 16; o > 0; o >>= 1) acc += __shfl_xor_sync(FULL, acc, o);

    __shared__ float wsum[4];
    __shared__ int   s_last;
    if (lane == 0) wsum[wid] = acc;
    __syncthreads();

    if (tid == 0) {
        g_partials[bid] = wsum[0] + wsum[1] + wsum[2] + wsum[3];
        __threadfence();
        unsigned ticket = atomicAdd(&g_count, 1u);
        s_last = (ticket == GRID - 1) ? 1 : 0;
    }
    __syncthreads();

    // ---- last block: deterministic fixed-order final sum of 296 partials ----
    if (s_last) {
        double v = 0.0;
        for (int i = tid; i < GRID; i += TPB) v += (double)g_partials[i];

        __shared__ double dsum[TPB];
        dsum[tid] = v;
        __syncthreads();
        #pragma unroll
        for (int o = TPB / 2; o > 0; o >>= 1) {
            if (tid < o) dsum[tid] += dsum[tid + o];
            __syncthreads();
        }
        if (tid == 0) {
            out[0] = (float)dsum[0];
            g_count = 0;                       // reset for next graph replay
        }
    }
}

extern "C" void kernel_launch(void* const* d_in, const int* in_sizes, int n_in,
                              void* d_out, int out_size)
{
    (void)in_sizes; (void)n_in; (void)out_size;
    const float* Ym = (const float*)d_in[0];
    const float* Xm = (const float*)d_in[1];
    const float* Yt = (const float*)d_in[2];
    const float* Xt = (const float*)d_in[3];

    cudaFuncSetAttribute(motion_loss_kernel,
                         cudaFuncAttributeMaxDynamicSharedMemorySize, SMEM_BYTES);
    motion_loss_kernel<<<GRID, TPB, SMEM_BYTES>>>(Ym, Xm, Yt, Xt, (float*)d_out);
}